// round 1
// baseline (speedup 1.0000x reference)
#include <cuda_runtime.h>
#include <math.h>

// Problem constants (fixed-shape problem: B=4, N=50000, E=800000, D=64)
#define NN 50000
#define BB 4
#define DD 64
#define BD (BB * DD)   // 256 floats = 1KB per node

// Scratch (allocation-free rule: __device__ globals)
__device__ float g_dis[NN];            // rsqrt(degree)
__device__ float g_xw [(size_t)NN * BD];  // linear output, (N, B, D) layout
__device__ float g_agg[(size_t)NN * BD];  // aggregation accumulator, (N, B, D)
__device__ float g_h1 [(size_t)NN * BD];  // layer-1 activation, (N, B, D)

// ---------------------------------------------------------------------------
// degree / normalization
// ---------------------------------------------------------------------------
__global__ void fill_deg_k() {
    int n = blockIdx.x * blockDim.x + threadIdx.x;
    if (n < NN) g_dis[n] = 1.0f;  // self-loop contributes 1
}

__global__ void count_deg_k(const int* __restrict__ ei, int E) {
    int e = blockIdx.x * blockDim.x + threadIdx.x;
    if (e < E) atomicAdd(&g_dis[ei[E + e]], 1.0f);  // targets = col = ei[1]
}

__global__ void rsqrt_deg_k() {
    int n = blockIdx.x * blockDim.x + threadIdx.x;
    if (n < NN) g_dis[n] = rsqrtf(g_dis[n]);  // deg >= 1 always
}

// ---------------------------------------------------------------------------
// GEMM: xw[(n*B+b)*D + d] = sum_k x[...k] * W[k*D+d]
// Also fuses self-loop init: agg = xw * dis[n]^2
// XBND=true:  x is (B, N, D)  (layer-1 input h)
// XBND=false: x is (N, B, D)  (layer-2 input g_h1)
// ---------------------------------------------------------------------------
template <bool XBND>
__global__ __launch_bounds__(256) void gemm_k(const float* __restrict__ x,
                                              const float* __restrict__ W) {
    __shared__ float Ws[DD * DD];     // 16 KB
    __shared__ float xs[4][DD];       // 1 KB
    const int tid = threadIdx.x;

    for (int i = tid; i < DD * DD; i += 256) Ws[i] = W[i];
    __syncthreads();

    const int rowBase = blockIdx.x * 16;   // 16 rows (n,b pairs) per block
    const int rloc = tid >> 6;             // 0..3
    const int d    = tid & 63;

    for (int g = 0; g < 16; g += 4) {
        // cooperative load of 4 input rows
        {
            const int rr = rowBase + g + rloc;
            float v = 0.0f;
            if (rr < NN * BB) {
                if (XBND) {
                    const int n = rr / BB, b = rr % BB;
                    v = x[((size_t)b * NN + n) * DD + d];
                } else {
                    v = x[(size_t)rr * DD + d];
                }
            }
            xs[rloc][d] = v;
        }
        __syncthreads();

        const int r = rowBase + g + rloc;
        if (r < NN * BB) {
            float acc = 0.0f;
#pragma unroll
            for (int k = 0; k < DD; k++) acc = fmaf(xs[rloc][k], Ws[k * DD + d], acc);
            g_xw[(size_t)r * DD + d] = acc;
            const float dn = g_dis[r / BB];
            g_agg[(size_t)r * DD + d] = acc * dn * dn;  // self-loop term
        }
        __syncthreads();
    }
}

// ---------------------------------------------------------------------------
// Edge scatter: agg[col] += xw[row] * dis[row]*dis[col]
// 64 threads per edge; each thread moves one float4 (16B) and issues one
// red.global.add.v4.f32.
// ---------------------------------------------------------------------------
__global__ __launch_bounds__(256) void scatter_k(const int* __restrict__ ei, int E) {
    const long gid  = (long)blockIdx.x * blockDim.x + threadIdx.x;
    const int  e    = (int)(gid >> 6);
    const int  lane = (int)(gid & 63);
    if (e >= E) return;

    const int r = ei[e];        // source
    const int c = ei[E + e];    // target
    const float norm = g_dis[r] * g_dis[c];

    const float4 v = __ldg(reinterpret_cast<const float4*>(g_xw + (size_t)r * BD) + lane);
    float* dst = g_agg + (size_t)c * BD + (size_t)lane * 4;
    asm volatile("red.global.add.v4.f32 [%0], {%1,%2,%3,%4};"
                 :: "l"(dst),
                    "f"(v.x * norm), "f"(v.y * norm), "f"(v.z * norm), "f"(v.w * norm)
                 : "memory");
}

// ---------------------------------------------------------------------------
// Activation: out = tanh(agg + bias). TO_BND converts (N,B,D) -> (B,N,D).
// ---------------------------------------------------------------------------
template <bool TO_BND>
__global__ __launch_bounds__(256) void act_k(const float* __restrict__ bias,
                                             float* __restrict__ out) {
    const long i = (long)blockIdx.x * blockDim.x + threadIdx.x;
    if (i >= (long)NN * BD) return;
    const int  d = (int)(i & 63);
    const long r = i >> 6;                 // r = n*B + b
    const float v = tanhf(g_agg[i] + bias[d]);
    if (TO_BND) {
        const long n = r / BB, b = r % BB;
        out[(b * (long)NN + n) * DD + d] = v;
    } else {
        out[i] = v;
    }
}

// ---------------------------------------------------------------------------
extern "C" void kernel_launch(void* const* d_in, const int* in_sizes, int n_in,
                              void* d_out, int out_size) {
    const float* h  = (const float*)d_in[1];
    const int*   ei = (const int*)d_in[2];
    const float* W1 = (const float*)d_in[3];
    const float* b1 = (const float*)d_in[4];
    const float* W2 = (const float*)d_in[5];
    const float* b2 = (const float*)d_in[6];
    float* out = (float*)d_out;

    const int E = in_sizes[2] / 2;

    const int nRows = NN * BB;
    const int gemmBlocks = (nRows + 15) / 16;
    const long scatterThreads = (long)E * 64;
    const int scatterBlocks = (int)((scatterThreads + 255) / 256);
    const int elemBlocks = (int)(((long)NN * BD + 255) / 256);

    // normalization
    fill_deg_k<<<(NN + 255) / 256, 256>>>();
    count_deg_k<<<(E + 255) / 256, 256>>>(ei, E);
    rsqrt_deg_k<<<(NN + 255) / 256, 256>>>();

    // layer 1
    gemm_k<true><<<gemmBlocks, 256>>>(h, W1);
    scatter_k<<<scatterBlocks, 256>>>(ei, E);
    act_k<false><<<elemBlocks, 256>>>(b1, nullptr ? nullptr : g_h1);

    // layer 2
    gemm_k<false><<<gemmBlocks, 256>>>(g_h1, W2);
    scatter_k<<<scatterBlocks, 256>>>(ei, E);
    act_k<true><<<elemBlocks, 256>>>(b2, out);
}

// round 2
// speedup vs baseline: 1.2467x; 1.2467x over previous
#include <cuda_runtime.h>
#include <math.h>

// Fixed-shape problem: B=4, N=50000, E=800000, D=64
#define NN 50000
#define BB 4
#define DD 64
#define EE 800000
#define NR (NN * BB)   // 200000 rows; node chunk = 4 rows = 256 floats = 64 float4

// Scratch (__device__ globals per allocation-free rule)
__device__ float4 g_xw[(size_t)NR * 16];   // linear output, (N,B,D) = 51.2 MB
__device__ float4 g_h1[(size_t)NR * 16];   // layer-1 activation, (N,B,D)
__device__ float  g_dis[NN];               // rsqrt(deg+1)
__device__ int    g_deg[NN];
__device__ int    g_off[NN + 1];           // CSR offsets (by target node)
__device__ int    g_cur[NN];               // fill cursors
__device__ int    g_src[EE];               // CSR source node per slot
__device__ float  g_nrm[EE];               // dis[src]*dis[dst] per slot

// ---------------------------------------------------------------------------
// degree / normalization / CSR build
// ---------------------------------------------------------------------------
__global__ void zero_k() {
    int n = blockIdx.x * blockDim.x + threadIdx.x;
    if (n < NN) g_deg[n] = 0;
}

__global__ void count_k(const int* __restrict__ ei, int E) {
    int e = blockIdx.x * blockDim.x + threadIdx.x;
    if (e < E) atomicAdd(&g_deg[ei[E + e]], 1);
}

__global__ void dis_k() {
    int n = blockIdx.x * blockDim.x + threadIdx.x;
    if (n < NN) g_dis[n] = rsqrtf((float)(g_deg[n] + 1));  // +1 self-loop
}

// single-block exclusive scan of g_deg -> g_off / g_cur
__global__ void scan_k() {
    __shared__ int part[1024];
    const int tid = threadIdx.x;
    const int CH = (NN + 1023) / 1024;   // 49
    const int base = tid * CH;
    int s = 0;
    for (int i = 0; i < CH; i++) {
        int idx = base + i;
        if (idx < NN) s += g_deg[idx];
    }
    part[tid] = s;
    __syncthreads();
    for (int o = 1; o < 1024; o <<= 1) {
        int v = (tid >= o) ? part[tid - o] : 0;
        __syncthreads();
        part[tid] += v;
        __syncthreads();
    }
    int run = part[tid] - s;   // exclusive prefix
    for (int i = 0; i < CH; i++) {
        int idx = base + i;
        if (idx < NN) {
            g_off[idx] = run;
            g_cur[idx] = run;
            run += g_deg[idx];
        } else if (idx == NN) {
            g_off[NN] = run;
        }
    }
}

__global__ void fill_k(const int* __restrict__ ei, int E) {
    int e = blockIdx.x * blockDim.x + threadIdx.x;
    if (e >= E) return;
    int r = ei[e];        // source
    int c = ei[E + e];    // target
    int pos = atomicAdd(&g_cur[c], 1);
    g_src[pos] = r;
    g_nrm[pos] = g_dis[r] * g_dis[c];
}

// ---------------------------------------------------------------------------
// GEMM: g_xw[r][d] = sum_k x[r][k] * W[k][d], register-tiled 2 rows x 8 cols.
// 64 rows x 64 cols per 256-thread block; NR = 200000 = 3125 * 64 exact.
// XBND: x is (B,N,D) (layer-1 h); else (N,B,D) (g_h1).
// ---------------------------------------------------------------------------
template <bool XBND>
__global__ __launch_bounds__(256) void gemm_k(const float* __restrict__ x,
                                              const float* __restrict__ W) {
    __shared__ __align__(16) float Ws[64 * 68];  // padded rows, 17.4 KB
    __shared__ float xs[64 * 65];                // padded rows, 16.6 KB
    const int tid = threadIdx.x;

    for (int i = tid; i < 4096; i += 256)
        Ws[(i >> 6) * 68 + (i & 63)] = W[i];

    const int base = blockIdx.x * 64;
    {
        const int rl = tid >> 6, d = tid & 63;
        for (int g = 0; g < 64; g += 4) {
            const int rr = base + g + rl;
            float v;
            if (XBND) {
                const int n = rr >> 2, b = rr & 3;
                v = x[((size_t)b * NN + n) * DD + d];
            } else {
                v = x[(size_t)rr * DD + d];
            }
            xs[(g + rl) * 65 + d] = v;
        }
    }
    __syncthreads();

    const int r2 = (tid >> 3) * 2;     // 0..62
    const int c8 = (tid & 7) * 8;      // 0..56
    float acc[2][8];
#pragma unroll
    for (int i = 0; i < 2; i++)
#pragma unroll
        for (int j = 0; j < 8; j++) acc[i][j] = 0.0f;

#pragma unroll 4
    for (int k = 0; k < 64; k++) {
        const float a0 = xs[r2 * 65 + k];
        const float a1 = xs[(r2 + 1) * 65 + k];
        const float4 w0 = *(const float4*)&Ws[k * 68 + c8];
        const float4 w1 = *(const float4*)&Ws[k * 68 + c8 + 4];
        acc[0][0] = fmaf(a0, w0.x, acc[0][0]);
        acc[0][1] = fmaf(a0, w0.y, acc[0][1]);
        acc[0][2] = fmaf(a0, w0.z, acc[0][2]);
        acc[0][3] = fmaf(a0, w0.w, acc[0][3]);
        acc[0][4] = fmaf(a0, w1.x, acc[0][4]);
        acc[0][5] = fmaf(a0, w1.y, acc[0][5]);
        acc[0][6] = fmaf(a0, w1.z, acc[0][6]);
        acc[0][7] = fmaf(a0, w1.w, acc[0][7]);
        acc[1][0] = fmaf(a1, w0.x, acc[1][0]);
        acc[1][1] = fmaf(a1, w0.y, acc[1][1]);
        acc[1][2] = fmaf(a1, w0.z, acc[1][2]);
        acc[1][3] = fmaf(a1, w0.w, acc[1][3]);
        acc[1][4] = fmaf(a1, w1.x, acc[1][4]);
        acc[1][5] = fmaf(a1, w1.y, acc[1][5]);
        acc[1][6] = fmaf(a1, w1.z, acc[1][6]);
        acc[1][7] = fmaf(a1, w1.w, acc[1][7]);
    }

    float* outp = (float*)g_xw;
#pragma unroll
    for (int i = 0; i < 2; i++) {
        const size_t row = (size_t)(base + r2 + i);
        float4 s0 = make_float4(acc[i][0], acc[i][1], acc[i][2], acc[i][3]);
        float4 s1 = make_float4(acc[i][4], acc[i][5], acc[i][6], acc[i][7]);
        *(float4*)&outp[row * DD + c8]     = s0;
        *(float4*)&outp[row * DD + c8 + 4] = s1;
    }
}

// ---------------------------------------------------------------------------
// Fused aggregation: per target node, 64-thread group accumulates
// self-loop + sum over in-edges of xw[src]*norm, then +bias, tanh, store.
// FINAL: write to out in (B,N,D); else to g_h1 in (N,B,D).
// ---------------------------------------------------------------------------
template <bool FINAL>
__global__ __launch_bounds__(256) void agg_k(const float* __restrict__ bias,
                                             float* __restrict__ dst) {
    const int node = blockIdx.x * 4 + (threadIdx.x >> 6);
    const int lane = threadIdx.x & 63;
    if (node >= NN) return;

    const float4* __restrict__ xw = g_xw;
    const float dn = g_dis[node];
    const float sl = dn * dn;
    float4 acc = __ldg(xw + (size_t)node * 64 + lane);
    acc.x *= sl; acc.y *= sl; acc.z *= sl; acc.w *= sl;

    const int end = g_off[node + 1];
#pragma unroll 2
    for (int j = g_off[node]; j < end; j++) {
        const int   r  = __ldg(g_src + j);
        const float nm = __ldg(g_nrm + j);
        const float4 v = __ldg(xw + (size_t)r * 64 + lane);
        acc.x = fmaf(v.x, nm, acc.x);
        acc.y = fmaf(v.y, nm, acc.y);
        acc.z = fmaf(v.z, nm, acc.z);
        acc.w = fmaf(v.w, nm, acc.w);
    }

    const float4 bv = __ldg((const float4*)bias + (lane & 15));
    float4 o;
    o.x = tanhf(acc.x + bv.x);
    o.y = tanhf(acc.y + bv.y);
    o.z = tanhf(acc.z + bv.z);
    o.w = tanhf(acc.w + bv.w);

    if (FINAL) {
        const int b = lane >> 4;   // batch
        ((float4*)dst)[((size_t)b * NN + node) * 16 + (lane & 15)] = o;
    } else {
        ((float4*)dst)[(size_t)node * 64 + lane] = o;
    }
}

// ---------------------------------------------------------------------------
extern "C" void kernel_launch(void* const* d_in, const int* in_sizes, int n_in,
                              void* d_out, int out_size) {
    const float* h  = (const float*)d_in[1];
    const int*   ei = (const int*)d_in[2];
    const float* b1 = (const float*)d_in[4];
    const float* W1 = (const float*)d_in[3];
    const float* W2 = (const float*)d_in[5];
    const float* b2 = (const float*)d_in[6];
    float* out = (float*)d_out;

    const int E = in_sizes[2] / 2;

    const int nB  = (NN + 255) / 256;
    const int eB  = (E + 255) / 256;
    const int gB  = NR / 64;          // 3125, exact
    const int aB  = (NN + 3) / 4;     // 12500

    // normalization + CSR (shared by both layers)
    zero_k <<<nB, 256>>>();
    count_k<<<eB, 256>>>(ei, E);
    dis_k  <<<nB, 256>>>();
    scan_k <<<1, 1024>>>();
    fill_k <<<eB, 256>>>(ei, E);

    // layer 1
    gemm_k<true> <<<gB, 256>>>(h, W1);
    agg_k<false> <<<aB, 256>>>(b1, (float*)g_h1);

    // layer 2
    gemm_k<false><<<gB, 256>>>((const float*)g_h1, W2);
    agg_k<true>  <<<aB, 256>>>(b2, out);
}

// round 3
// speedup vs baseline: 1.4069x; 1.1285x over previous
#include <cuda_runtime.h>
#include <math.h>

// Fixed-shape problem: B=4, N=50000, E=800000, D=64
#define NN 50000
#define BB 4
#define DD 64
#define EE 800000
#define NR (NN * BB)          // 200000 rows
#define SCAN_B 196            // ceil(50000/256)

// Scratch (__device__ globals per allocation-free rule)
__device__ float4 g_xw[(size_t)NR * 16];        // linear output, (N,B,D) = 51.2 MB
__device__ float4 g_h1[(size_t)NR * 16];        // layer-1 activation, (N,B,D)
__device__ float  g_dis[NN];                    // rsqrt(deg+1)
__device__ int    g_deg[NN];
__device__ int    g_off[NN + 1];                // CSR offsets (by target node)
__device__ int    g_cur[NN];                    // fill cursors
__device__ unsigned long long g_edge[EE];       // packed (src, nrm)
__device__ int    g_bsum[SCAN_B];               // block sums for scan

// ---------------------------------------------------------------------------
// degree count
// ---------------------------------------------------------------------------
__global__ void zero_k() {
    int n = blockIdx.x * blockDim.x + threadIdx.x;
    if (n < NN) g_deg[n] = 0;
}

__global__ void count_k(const int* __restrict__ ei, int E) {
    int e = blockIdx.x * blockDim.x + threadIdx.x;
    if (e < E) atomicAdd(&g_deg[ei[E + e]], 1);
}

// ---------------------------------------------------------------------------
// 3-phase exclusive scan of g_deg (also emits g_dis in phase 1)
// ---------------------------------------------------------------------------
__global__ __launch_bounds__(256) void scan1_k() {
    __shared__ int sh[256];
    const int tid = threadIdx.x;
    const int idx = blockIdx.x * 256 + tid;
    int v = (idx < NN) ? g_deg[idx] : 0;
    if (idx < NN) g_dis[idx] = rsqrtf((float)(v + 1));  // +1 self-loop
    sh[tid] = v;
    __syncthreads();
#pragma unroll
    for (int o = 1; o < 256; o <<= 1) {
        int t = (tid >= o) ? sh[tid - o] : 0;
        __syncthreads();
        sh[tid] += t;
        __syncthreads();
    }
    if (idx < NN) g_off[idx] = sh[tid] - v;   // exclusive within block
    if (tid == 255) g_bsum[blockIdx.x] = sh[255];
}

__global__ __launch_bounds__(256) void scan2_k() {
    __shared__ int sh[256];
    const int tid = threadIdx.x;
    int v = (tid < SCAN_B) ? g_bsum[tid] : 0;
    sh[tid] = v;
    __syncthreads();
#pragma unroll
    for (int o = 1; o < 256; o <<= 1) {
        int t = (tid >= o) ? sh[tid - o] : 0;
        __syncthreads();
        sh[tid] += t;
        __syncthreads();
    }
    if (tid < SCAN_B) g_bsum[tid] = sh[tid] - v;  // exclusive
}

__global__ __launch_bounds__(256) void scan3_k(int E) {
    const int idx = blockIdx.x * 256 + threadIdx.x;
    if (idx < NN) {
        int o = g_off[idx] + g_bsum[blockIdx.x];
        g_off[idx] = o;
        g_cur[idx] = o;
    }
    if (idx == 0) g_off[NN] = E;
}

__global__ void fill_k(const int* __restrict__ ei, int E) {
    int e = blockIdx.x * blockDim.x + threadIdx.x;
    if (e >= E) return;
    int r = ei[e];        // source
    int c = ei[E + e];    // target
    int pos = atomicAdd(&g_cur[c], 1);
    float nm = g_dis[r] * g_dis[c];
    g_edge[pos] = (unsigned long long)(unsigned int)r |
                  ((unsigned long long)__float_as_uint(nm) << 32);
}

// ---------------------------------------------------------------------------
// GEMM: g_xw[r][d] = sum_k x[r][k] * W[k][d], register-tiled 2 rows x 8 cols.
// XBND: x is (B,N,D) (layer-1 h); else (N,B,D) (g_h1).
// ---------------------------------------------------------------------------
template <bool XBND>
__global__ __launch_bounds__(256) void gemm_k(const float* __restrict__ x,
                                              const float* __restrict__ W) {
    __shared__ __align__(16) float Ws[64 * 68];
    __shared__ float xs[64 * 65];
    const int tid = threadIdx.x;

    for (int i = tid; i < 4096; i += 256)
        Ws[(i >> 6) * 68 + (i & 63)] = W[i];

    const int base = blockIdx.x * 64;
    {
        const int rl = tid >> 6, d = tid & 63;
        for (int g = 0; g < 64; g += 4) {
            const int rr = base + g + rl;
            float v;
            if (XBND) {
                const int n = rr >> 2, b = rr & 3;
                v = x[((size_t)b * NN + n) * DD + d];
            } else {
                v = x[(size_t)rr * DD + d];
            }
            xs[(g + rl) * 65 + d] = v;
        }
    }
    __syncthreads();

    const int r2 = (tid >> 3) * 2;
    const int c8 = (tid & 7) * 8;
    float acc[2][8];
#pragma unroll
    for (int i = 0; i < 2; i++)
#pragma unroll
        for (int j = 0; j < 8; j++) acc[i][j] = 0.0f;

#pragma unroll 4
    for (int k = 0; k < 64; k++) {
        const float a0 = xs[r2 * 65 + k];
        const float a1 = xs[(r2 + 1) * 65 + k];
        const float4 w0 = *(const float4*)&Ws[k * 68 + c8];
        const float4 w1 = *(const float4*)&Ws[k * 68 + c8 + 4];
        acc[0][0] = fmaf(a0, w0.x, acc[0][0]);
        acc[0][1] = fmaf(a0, w0.y, acc[0][1]);
        acc[0][2] = fmaf(a0, w0.z, acc[0][2]);
        acc[0][3] = fmaf(a0, w0.w, acc[0][3]);
        acc[0][4] = fmaf(a0, w1.x, acc[0][4]);
        acc[0][5] = fmaf(a0, w1.y, acc[0][5]);
        acc[0][6] = fmaf(a0, w1.z, acc[0][6]);
        acc[0][7] = fmaf(a0, w1.w, acc[0][7]);
        acc[1][0] = fmaf(a1, w0.x, acc[1][0]);
        acc[1][1] = fmaf(a1, w0.y, acc[1][1]);
        acc[1][2] = fmaf(a1, w0.z, acc[1][2]);
        acc[1][3] = fmaf(a1, w0.w, acc[1][3]);
        acc[1][4] = fmaf(a1, w1.x, acc[1][4]);
        acc[1][5] = fmaf(a1, w1.y, acc[1][5]);
        acc[1][6] = fmaf(a1, w1.z, acc[1][6]);
        acc[1][7] = fmaf(a1, w1.w, acc[1][7]);
    }

    float* outp = (float*)g_xw;
#pragma unroll
    for (int i = 0; i < 2; i++) {
        const size_t row = (size_t)(base + r2 + i);
        *(float4*)&outp[row * DD + c8]     = make_float4(acc[i][0], acc[i][1], acc[i][2], acc[i][3]);
        *(float4*)&outp[row * DD + c8 + 4] = make_float4(acc[i][4], acc[i][5], acc[i][6], acc[i][7]);
    }
}

// ---------------------------------------------------------------------------
// Fused aggregation: per target node (64 threads), self-loop + in-edge sum,
// +bias, tanh. Edge loop unrolled x4 with batched index loads for MLP=4.
// ---------------------------------------------------------------------------
template <bool FINAL>
__global__ __launch_bounds__(256) void agg_k(const float* __restrict__ bias,
                                             float* __restrict__ dst) {
    const int node = blockIdx.x * 4 + (threadIdx.x >> 6);
    const int lane = threadIdx.x & 63;
    if (node >= NN) return;

    const float4* __restrict__ xw = g_xw;
    const float dn = g_dis[node];
    const float sl = dn * dn;
    float4 acc = __ldg(xw + (size_t)node * 64 + lane);
    acc.x *= sl; acc.y *= sl; acc.z *= sl; acc.w *= sl;

    const int beg = g_off[node];
    const int end = g_off[node + 1];
    int j = beg;

    for (; j + 4 <= end; j += 4) {
        const unsigned long long e0 = __ldg(g_edge + j);
        const unsigned long long e1 = __ldg(g_edge + j + 1);
        const unsigned long long e2 = __ldg(g_edge + j + 2);
        const unsigned long long e3 = __ldg(g_edge + j + 3);
        const float4 v0 = __ldg(xw + (size_t)(unsigned int)(e0 & 0xffffffffu) * 64 + lane);
        const float4 v1 = __ldg(xw + (size_t)(unsigned int)(e1 & 0xffffffffu) * 64 + lane);
        const float4 v2 = __ldg(xw + (size_t)(unsigned int)(e2 & 0xffffffffu) * 64 + lane);
        const float4 v3 = __ldg(xw + (size_t)(unsigned int)(e3 & 0xffffffffu) * 64 + lane);
        const float n0 = __uint_as_float((unsigned int)(e0 >> 32));
        const float n1 = __uint_as_float((unsigned int)(e1 >> 32));
        const float n2 = __uint_as_float((unsigned int)(e2 >> 32));
        const float n3 = __uint_as_float((unsigned int)(e3 >> 32));
        acc.x = fmaf(v0.x, n0, acc.x); acc.y = fmaf(v0.y, n0, acc.y);
        acc.z = fmaf(v0.z, n0, acc.z); acc.w = fmaf(v0.w, n0, acc.w);
        acc.x = fmaf(v1.x, n1, acc.x); acc.y = fmaf(v1.y, n1, acc.y);
        acc.z = fmaf(v1.z, n1, acc.z); acc.w = fmaf(v1.w, n1, acc.w);
        acc.x = fmaf(v2.x, n2, acc.x); acc.y = fmaf(v2.y, n2, acc.y);
        acc.z = fmaf(v2.z, n2, acc.z); acc.w = fmaf(v2.w, n2, acc.w);
        acc.x = fmaf(v3.x, n3, acc.x); acc.y = fmaf(v3.y, n3, acc.y);
        acc.z = fmaf(v3.z, n3, acc.z); acc.w = fmaf(v3.w, n3, acc.w);
    }
    for (; j < end; j++) {
        const unsigned long long e = __ldg(g_edge + j);
        const float4 v = __ldg(xw + (size_t)(unsigned int)(e & 0xffffffffu) * 64 + lane);
        const float nm = __uint_as_float((unsigned int)(e >> 32));
        acc.x = fmaf(v.x, nm, acc.x); acc.y = fmaf(v.y, nm, acc.y);
        acc.z = fmaf(v.z, nm, acc.z); acc.w = fmaf(v.w, nm, acc.w);
    }

    const float4 bv = __ldg((const float4*)bias + (lane & 15));
    float4 o;
    o.x = tanhf(acc.x + bv.x);
    o.y = tanhf(acc.y + bv.y);
    o.z = tanhf(acc.z + bv.z);
    o.w = tanhf(acc.w + bv.w);

    if (FINAL) {
        const int b = lane >> 4;
        ((float4*)dst)[((size_t)b * NN + node) * 16 + (lane & 15)] = o;
    } else {
        ((float4*)dst)[(size_t)node * 64 + lane] = o;
    }
}

// ---------------------------------------------------------------------------
extern "C" void kernel_launch(void* const* d_in, const int* in_sizes, int n_in,
                              void* d_out, int out_size) {
    const float* h  = (const float*)d_in[1];
    const int*   ei = (const int*)d_in[2];
    const float* W1 = (const float*)d_in[3];
    const float* b1 = (const float*)d_in[4];
    const float* W2 = (const float*)d_in[5];
    const float* b2 = (const float*)d_in[6];
    float* out = (float*)d_out;

    const int E = in_sizes[2] / 2;

    const int nB = (NN + 255) / 256;   // 196
    const int eB = (E + 255) / 256;
    const int gB = NR / 64;            // 3125
    const int aB = (NN + 3) / 4;       // 12500

    // normalization + CSR (shared by both layers)
    zero_k <<<nB, 256>>>();
    count_k<<<eB, 256>>>(ei, E);
    scan1_k<<<nB, 256>>>();
    scan2_k<<<1, 256>>>();
    scan3_k<<<nB, 256>>>(E);
    fill_k <<<eB, 256>>>(ei, E);

    // layer 1
    gemm_k<true> <<<gB, 256>>>(h, W1);
    agg_k<false> <<<aB, 256>>>(b1, (float*)g_h1);

    // layer 2
    gemm_k<false><<<gB, 256>>>((const float*)g_h1, W2);
    agg_k<true>  <<<aB, 256>>>(b2, out);
}